// round 13
// baseline (speedup 1.0000x reference)
#include <cuda_runtime.h>
#include <cuda_fp16.h>

#define NN 100000
#define NN2 200000
#define DD 128
#define EE 1600000
#define DEE 16
#define GG 512
#define BN_EPS 1e-5f
#define NCHUNK 2
#define CHUNKN 50000

typedef unsigned long long u64;

// ---------------- f32x2 packed helpers -----------------------------------------
__device__ __forceinline__ void ffma2(u64& d, u64 a, u64 b) {
    asm("fma.rn.f32x2 %0, %1, %2, %0;" : "+l"(d) : "l"(a), "l"(b));
}
__device__ __forceinline__ u64 pack_dup(float x) {
    u64 d; unsigned xi = __float_as_uint(x);
    asm("mov.b64 %0, {%1, %1};" : "=l"(d) : "r"(xi));
    return d;
}
__device__ __forceinline__ float2 unpack2(u64 v) {
    unsigned lo, hi;
    asm("mov.b64 {%0, %1}, %2;" : "=r"(lo), "=r"(hi) : "l"(v));
    return make_float2(__uint_as_float(lo), __uint_as_float(hi));
}

// ---------------- scratch (static device globals; no allocation) -----------------
__device__ __align__(16) __half g_bufA[NN * DD];         // 25.6 MB layer-1 xw' fp16
__device__ __align__(16) __half g_bufC[NN * DD];         // 25.6 MB layer-2 xw' fp16
__device__ __align__(16) float g_bufB[NN * DD];          // 51.2 MB h (fp32)
__device__ int   g_deg2[NN2];
__device__ int   g_rowptr[NN + 1];
__device__ int   g_sptr[NN + 1];
__device__ int   g_curn[NN];
__device__ int   g_curs[NN];
__device__ int   g_csrsrc[EE];
__device__ int   g_eid[EE];
__device__ int   g_src32[EE];
__device__ int   g_dst32[EE];
__device__ int   g_egptr[GG + 1];
__device__ int   g_nptr[GG + 1];
__device__ float g_dinv[NN];
__device__ float g_hsum[GG * DD];
__device__ int   g_blksums[256];
__device__ int   g_is64;

// ---------------- index helpers (dtype-agnostic) ----------------------------------
__device__ __forceinline__ int load_idx(const void* p, long long i) {
    if (g_is64) return (int)((const long long*)p)[i];
    return ((const int*)p)[i];
}
__device__ __forceinline__ int clampi(int v, int lo, int hi) {
    return v < lo ? lo : (v > hi ? hi : v);
}
// add 8 halfs (uint4) into acc[8]
__device__ __forceinline__ void add8(float* a, uint4 u) {
    float2 f;
    f = __half22float2(*reinterpret_cast<__half2*>(&u.x)); a[0] += f.x; a[1] += f.y;
    f = __half22float2(*reinterpret_cast<__half2*>(&u.y)); a[2] += f.x; a[3] += f.y;
    f = __half22float2(*reinterpret_cast<__half2*>(&u.z)); a[4] += f.x; a[5] += f.y;
    f = __half22float2(*reinterpret_cast<__half2*>(&u.w)); a[6] += f.x; a[7] += f.y;
}

// ---------------- init + dtype detect in one kernel -----------------------------------
__global__ void k_initdetect(const int* __restrict__ w) {
    if (blockIdx.x == 0) {
        __shared__ int ok;
        if (threadIdx.x == 0) ok = 1;
        __syncthreads();
        int bad = 0;
        for (int i = threadIdx.x; i < 2048; i += blockDim.x)
            if (w[2 * i + 1] != 0) bad = 1;
        if (bad) atomicAnd(&ok, 0);
        __syncthreads();
        if (threadIdx.x == 0) g_is64 = ok;
    }
    int i = blockIdx.x * blockDim.x + threadIdx.x;
    int stride = gridDim.x * blockDim.x;
    for (int j = i; j < NN2; j += stride) g_deg2[j] = 0;
    for (int j = i; j < GG * DD; j += stride) g_hsum[j] = 0.f;
}

// ---------------- convert + histogram in one pass --------------------------------------
__global__ void k_converthist(const void* __restrict__ ei) {
    int e = blockIdx.x * blockDim.x + threadIdx.x;
    if (e >= EE) return;
    int s = clampi(load_idx(ei, e), 0, NN - 1);
    int d = clampi(load_idx(ei, (long long)EE + e), 0, NN - 1);
    g_src32[e] = s;
    g_dst32[e] = d;
    atomicAdd(&g_deg2[d], 1);
    atomicAdd(&g_deg2[NN + s], 1);
}

// ---------------- 3-phase exclusive scan over g_deg2[0..200k); scan1 also emits dinv -----
__global__ void k_scan1() {
    __shared__ int s[1024];
    int b = blockIdx.x, t = threadIdx.x;
    int i = b * 1024 + t;
    int v = (i < NN2) ? g_deg2[i] : 0;
    if (i < NN) g_dinv[i] = rsqrtf((float)(v + 1));   // dst degree + self-loop
    s[t] = v;
    __syncthreads();
    for (int off = 1; off < 1024; off <<= 1) {
        int x = (t >= off) ? s[t - off] : 0;
        __syncthreads();
        s[t] += x;
        __syncthreads();
    }
    if (i < NN2) {
        if (i < NN) g_rowptr[i] = s[t] - v;
        else        g_sptr[i - NN] = s[t] - v;
    }
    if (t == 1023) g_blksums[b] = s[t];
}

__global__ void k_scan2(int nb) {
    __shared__ int s[256];
    int t = threadIdx.x;
    int v = (t < nb) ? g_blksums[t] : 0;
    s[t] = v;
    __syncthreads();
    for (int off = 1; off < 256; off <<= 1) {
        int x = (t >= off) ? s[t - off] : 0;
        __syncthreads();
        s[t] += x;
        __syncthreads();
    }
    g_blksums[t] = s[t] - v;
}

__global__ void k_scan3() {
    int b = blockIdx.x, t = threadIdx.x;
    int i = b * 1024 + t;
    if (i < NN2) {
        int add = g_blksums[b];
        if (i < NN) {
            int rp = g_rowptr[i] + add;
            g_rowptr[i] = rp;
            g_curn[i] = rp;
        } else {
            int sp = g_sptr[i - NN] + add - EE;
            g_sptr[i - NN] = sp;
            g_curs[i - NN] = sp;
        }
    }
    if (i == 0) { g_rowptr[NN] = EE; g_sptr[NN] = EE; }
}

// ---------------- nptr via binary search on sorted batch; egptr = sptr[nptr] ------------
__global__ void k_nptr(const void* __restrict__ batch) {
    int g = threadIdx.x;    // 512
    int lo = 0, hi = NN;
    while (lo < hi) {
        int mid = (lo + hi) >> 1;
        if (load_idx(batch, mid) < g) lo = mid + 1;
        else hi = mid;
    }
    g_nptr[g] = lo;
    g_egptr[g] = g_sptr[lo];
    if (g == 0) { g_nptr[GG] = NN; g_egptr[GG] = EE; }
}

// ---------------- CSR scatters (split, independent) ----------------------------------------
__global__ void k_scatter_dst() {
    int e = blockIdx.x * blockDim.x + threadIdx.x;
    if (e >= EE) return;
    int s = g_src32[e];
    int d = g_dst32[e];
    int p = atomicAdd(&g_curn[d], 1);
    if (p >= 0 && p < EE) g_csrsrc[p] = s;
}

__global__ void k_scatter_src() {
    int e = blockIdx.x * blockDim.x + threadIdx.x;
    if (e >= EE) return;
    int s = g_src32[e];
    int p2 = atomicAdd(&g_curs[s], 1);
    if (p2 >= 0 && p2 < EE) g_eid[p2] = e;
}

// ---------------- GEMM (FFMA2, 8x8 regtile, double-buffered) -------------------------------
#define XPAD 132
template <bool FIRST, bool OUTC>
__global__ void __launch_bounds__(256, 2)
k_gemm(const float* __restrict__ Xext, const float* __restrict__ W, int rstart, int rend) {
    const float* __restrict__ X = FIRST ? Xext : (const float*)g_bufB;
    __half* __restrict__ Y = OUTC ? g_bufC : g_bufA;
    __shared__ __align__(16) float xs[2][16][XPAD];
    __shared__ __align__(16) float ws[2][16][128];
    int tid = threadIdx.x;
    int c = tid & 15;
    int r = tid >> 4;
    int row0 = rstart + blockIdx.x * 128;

    int x_kq = tid & 3;
    int x_rr0 = tid >> 2;

    u64 acc2[8][4];
#pragma unroll
    for (int i = 0; i < 8; i++)
#pragma unroll
        for (int j = 0; j < 4; j++) acc2[i][j] = 0ull;

#pragma unroll
    for (int l = 0; l < 2; l++) {
        int rr = x_rr0 + l * 64;
        int grow = row0 + rr;
        float4 v = make_float4(0.f, 0.f, 0.f, 0.f);
        if (grow < rend)
            v = *reinterpret_cast<const float4*>(&X[grow * DD + x_kq * 4]);
        xs[0][x_kq * 4 + 0][rr] = v.x;
        xs[0][x_kq * 4 + 1][rr] = v.y;
        xs[0][x_kq * 4 + 2][rr] = v.z;
        xs[0][x_kq * 4 + 3][rr] = v.w;
    }
#pragma unroll
    for (int l = 0; l < 8; l++) {
        int idx = tid + l * 256;
        ws[0][idx >> 7][idx & 127] = W[(idx >> 7) * DD + (idx & 127)];
    }
    __syncthreads();

    for (int it = 0; it < 8; it++) {
        int cur = it & 1;
        float4 nx[2];
        float nw[8];
        if (it < 7) {
            int kc = (it + 1) * 16;
#pragma unroll
            for (int l = 0; l < 2; l++) {
                int rr = x_rr0 + l * 64;
                int grow = row0 + rr;
                nx[l] = make_float4(0.f, 0.f, 0.f, 0.f);
                if (grow < rend)
                    nx[l] = *reinterpret_cast<const float4*>(&X[grow * DD + kc + x_kq * 4]);
            }
#pragma unroll
            for (int l = 0; l < 8; l++) {
                int idx = tid + l * 256;
                nw[l] = W[(kc + (idx >> 7)) * DD + (idx & 127)];
            }
        }
#pragma unroll
        for (int k = 0; k < 16; k++) {
            float4 xa = *reinterpret_cast<float4*>(&xs[cur][k][r * 8]);
            float4 xb = *reinterpret_cast<float4*>(&xs[cur][k][r * 8 + 4]);
            ulonglong2 w01 = *reinterpret_cast<ulonglong2*>(&ws[cur][k][c * 8]);
            ulonglong2 w23 = *reinterpret_cast<ulonglong2*>(&ws[cur][k][c * 8 + 4]);
            u64 wp[4] = {w01.x, w01.y, w23.x, w23.y};
            u64 xr2[8] = {pack_dup(xa.x), pack_dup(xa.y), pack_dup(xa.z), pack_dup(xa.w),
                          pack_dup(xb.x), pack_dup(xb.y), pack_dup(xb.z), pack_dup(xb.w)};
#pragma unroll
            for (int i = 0; i < 8; i++)
#pragma unroll
                for (int j = 0; j < 4; j++)
                    ffma2(acc2[i][j], xr2[i], wp[j]);
        }
        if (it < 7) {
            int nxt = cur ^ 1;
#pragma unroll
            for (int l = 0; l < 2; l++) {
                int rr = x_rr0 + l * 64;
                xs[nxt][x_kq * 4 + 0][rr] = nx[l].x;
                xs[nxt][x_kq * 4 + 1][rr] = nx[l].y;
                xs[nxt][x_kq * 4 + 2][rr] = nx[l].z;
                xs[nxt][x_kq * 4 + 3][rr] = nx[l].w;
            }
#pragma unroll
            for (int l = 0; l < 8; l++) {
                int idx = tid + l * 256;
                ws[nxt][idx >> 7][idx & 127] = nw[l];
            }
        }
        __syncthreads();
    }
#pragma unroll
    for (int i = 0; i < 8; i++) {
        int grow = row0 + r * 8 + i;
        if (grow < rend) {
            float d = g_dinv[grow];
            float2 p0 = unpack2(acc2[i][0]);
            float2 p1 = unpack2(acc2[i][1]);
            float2 p2 = unpack2(acc2[i][2]);
            float2 p3 = unpack2(acc2[i][3]);
            __half2 hh[4];
            hh[0] = __floats2half2_rn(p0.x * d, p0.y * d);
            hh[1] = __floats2half2_rn(p1.x * d, p1.y * d);
            hh[2] = __floats2half2_rn(p2.x * d, p2.y * d);
            hh[3] = __floats2half2_rn(p3.x * d, p3.y * d);
            *reinterpret_cast<uint4*>(&Y[grow * DD + c * 8]) = *reinterpret_cast<uint4*>(hh);
        }
    }
}

// ---------------- gather: 2 nodes per warp, uint4 per lane ----------------------------------
// half-warp hl (16 lanes x 16B = 256B row). SRCC selects payload buffer.
template <bool SRCC>
__global__ void k_gather(const float* __restrict__ B, const float* __restrict__ GA,
                         const float* __restrict__ BT, const float* __restrict__ M,
                         const float* __restrict__ V, int nstart, int ncount) {
    int w = (blockIdx.x * blockDim.x + threadIdx.x) >> 5;
    int lane = threadIdx.x & 31;
    int half = lane >> 4;
    int hl = lane & 15;
    int rel = w * 2 + half;
    if (rel >= ncount) return;
    int node = nstart + rel;
    float di = g_dinv[node];
    const uint4* xw4 = reinterpret_cast<const uint4*>(SRCC ? (const __half*)g_bufC
                                                           : (const __half*)g_bufA);
    float A0[8] = {0,0,0,0,0,0,0,0};
    float A1[8] = {0,0,0,0,0,0,0,0};
    float A2[8] = {0,0,0,0,0,0,0,0};
    float A3[8] = {0,0,0,0,0,0,0,0};
    add8(A0, xw4[node * 16 + hl]);           // self term (already * dinv_node)
    int jb = g_rowptr[node], je = g_rowptr[node + 1];
    int j = jb;
    for (; j + 3 < je; j += 4) {
        int s0 = g_csrsrc[j + 0];
        int s1 = g_csrsrc[j + 1];
        int s2 = g_csrsrc[j + 2];
        int s3 = g_csrsrc[j + 3];
        uint4 u0 = xw4[s0 * 16 + hl];
        uint4 u1 = xw4[s1 * 16 + hl];
        uint4 u2 = xw4[s2 * 16 + hl];
        uint4 u3 = xw4[s3 * 16 + hl];
        add8(A0, u0); add8(A1, u1); add8(A2, u2); add8(A3, u3);
    }
    for (; j < je; j++) add8(A0, xw4[g_csrsrc[j] * 16 + hl]);

    int f = hl * 8;
    float4 b4a  = *reinterpret_cast<const float4*>(&B[f]);
    float4 b4b  = *reinterpret_cast<const float4*>(&B[f + 4]);
    float4 g4a  = *reinterpret_cast<const float4*>(&GA[f]);
    float4 g4b  = *reinterpret_cast<const float4*>(&GA[f + 4]);
    float4 bt4a = *reinterpret_cast<const float4*>(&BT[f]);
    float4 bt4b = *reinterpret_cast<const float4*>(&BT[f + 4]);
    float4 m4a  = *reinterpret_cast<const float4*>(&M[f]);
    float4 m4b  = *reinterpret_cast<const float4*>(&M[f + 4]);
    float4 v4a  = *reinterpret_cast<const float4*>(&V[f]);
    float4 v4b  = *reinterpret_cast<const float4*>(&V[f + 4]);
    float bb[8] = {b4a.x, b4a.y, b4a.z, b4a.w, b4b.x, b4b.y, b4b.z, b4b.w};
    float gg[8] = {g4a.x, g4a.y, g4a.z, g4a.w, g4b.x, g4b.y, g4b.z, g4b.w};
    float bt[8] = {bt4a.x, bt4a.y, bt4a.z, bt4a.w, bt4b.x, bt4b.y, bt4b.z, bt4b.w};
    float mm[8] = {m4a.x, m4a.y, m4a.z, m4a.w, m4b.x, m4b.y, m4b.z, m4b.w};
    float vv[8] = {v4a.x, v4a.y, v4a.z, v4a.w, v4b.x, v4b.y, v4b.z, v4b.w};
    float o[8];
#pragma unroll
    for (int i = 0; i < 8; i++) {
        float acc = (A0[i] + A1[i]) + (A2[i] + A3[i]);
        o[i] = fmaxf((acc * di + bb[i] - mm[i]) * rsqrtf(vv[i] + BN_EPS) * gg[i] + bt[i], 0.f);
    }
    float4* out4 = reinterpret_cast<float4*>((float*)g_bufB);
    out4[node * 32 + hl * 2 + 0] = make_float4(o[0], o[1], o[2], o[3]);
    out4[node * 32 + hl * 2 + 1] = make_float4(o[4], o[5], o[6], o[7]);
}

// ---------------- edge MLP first layer, summed per graph (FFMA2, 2-edge ILP) -----------------
#define EBLK 8
__global__ void k_edgemlp(const float* __restrict__ EA, const float* __restrict__ W1e,
                          const float* __restrict__ B1e) {
    int g = blockIdx.x >> 3;
    int q = blockIdx.x & (EBLK - 1);
    int tid = threadIdx.x, warp = tid >> 5, lane = tid & 31;
    __shared__ float eas[8][2][16];
    __shared__ float red[DD];
    ulonglong2 wc[16];
#pragma unroll
    for (int k = 0; k < 16; k++)
        wc[k] = *reinterpret_cast<const ulonglong2*>(&W1e[k * DD + lane * 4]);
    ulonglong2 b2 = *reinterpret_cast<const ulonglong2*>(&B1e[lane * 4]);

    int gb = g_egptr[g], ge = g_egptr[g + 1];
    int cnt = ge - gb;
    int per = (cnt + EBLK - 1) / EBLK;
    int jb = gb + q * per;
    int je = min(jb + per, ge);

    float4 acc = make_float4(0.f, 0.f, 0.f, 0.f);
    for (int j = jb + warp; j < je; j += 16) {
        int j2 = j + 8;
        bool has2 = (j2 < je);
        int e0 = g_eid[j];
        int e1 = has2 ? g_eid[j2] : e0;
        if (lane < 16) eas[warp][0][lane] = EA[(long long)e0 * DEE + lane];
        else           eas[warp][1][lane - 16] = EA[(long long)e1 * DEE + (lane - 16)];
        __syncwarp();
        u64 h0 = b2.x, h1 = b2.y, h2 = b2.x, h3 = b2.y;
#pragma unroll
        for (int k = 0; k < 16; k++) {
            u64 p0 = pack_dup(eas[warp][0][k]);
            u64 p1 = pack_dup(eas[warp][1][k]);
            ffma2(h0, p0, wc[k].x);
            ffma2(h1, p0, wc[k].y);
            ffma2(h2, p1, wc[k].x);
            ffma2(h3, p1, wc[k].y);
        }
        float2 u0 = unpack2(h0), u1 = unpack2(h1);
        acc.x += fmaxf(u0.x, 0.f);
        acc.y += fmaxf(u0.y, 0.f);
        acc.z += fmaxf(u1.x, 0.f);
        acc.w += fmaxf(u1.y, 0.f);
        if (has2) {
            float2 u2 = unpack2(h2), u3 = unpack2(h3);
            acc.x += fmaxf(u2.x, 0.f);
            acc.y += fmaxf(u2.y, 0.f);
            acc.z += fmaxf(u3.x, 0.f);
            acc.w += fmaxf(u3.y, 0.f);
        }
        __syncwarp();
    }
    if (tid < DD) red[tid] = 0.f;
    __syncthreads();
    int f = lane * 4;
    atomicAdd(&red[f + 0], acc.x);
    atomicAdd(&red[f + 1], acc.y);
    atomicAdd(&red[f + 2], acc.z);
    atomicAdd(&red[f + 3], acc.w);
    __syncthreads();
    if (tid < DD) atomicAdd(&g_hsum[g * DD + tid], red[tid]);
}

// ---------------- final combine: node segment-mean + edge GEMM ----------------------------
__global__ void k_final(const float* __restrict__ We2, const float* __restrict__ be2,
                        float* __restrict__ out) {
    int g = blockIdx.x;
    int t = threadIdx.x;   // 128
    __shared__ float hm[DD];
    int ec = g_egptr[g + 1] - g_egptr[g];
    float inv_e = (ec > 0) ? (1.f / (float)ec) : 0.f;
    hm[t] = g_hsum[g * DD + t] * inv_e;

    int ns = g_nptr[g], ne = g_nptr[g + 1];
    const float* __restrict__ H = (const float*)g_bufB;
    float a0 = 0.f, a1 = 0.f, a2 = 0.f, a3 = 0.f;
    int rr = ns;
    for (; rr + 3 < ne; rr += 4) {
        a0 += H[(long long)rr * DD + t];
        a1 += H[(long long)(rr + 1) * DD + t];
        a2 += H[(long long)(rr + 2) * DD + t];
        a3 += H[(long long)(rr + 3) * DD + t];
    }
    for (; rr < ne; rr++) a0 += H[(long long)rr * DD + t];
    float nsumv = (a0 + a1) + (a2 + a3);

    __syncthreads();
    float acc = be2[t];
#pragma unroll 4
    for (int k = 0; k < DD; k++)
        acc = fmaf(hm[k], We2[k * DD + t], acc);
    if (ec == 0) acc = 0.f;
    int nc = ne - ns;
    float gr = nsumv / fmaxf((float)nc, 1.f);
    out[g * DD + t] = gr + acc;
}

// ---------------- launch ------------------------------------------------------------------------
extern "C" void kernel_launch(void* const* d_in, const int* in_sizes, int n_in,
                              void* d_out, int out_size) {
    const float* x = 0;  const void* ei = 0;  const void* batch = 0;  const float* ea = 0;
    const float* w16k[3] = {0, 0, 0};
    const float* v128[12] = {0};
    const float* We1 = 0;
    int n16k = 0, n128 = 0;
    for (int i = 0; i < n_in; i++) {
        long long sz = in_sizes[i];
        if      (sz == (long long)NN * DD) { if (!x) x = (const float*)d_in[i]; }
        else if (sz == 2LL * EE)           { if (!ei) ei = d_in[i]; }
        else if (sz == NN)                 { if (!batch) batch = d_in[i]; }
        else if (sz == (long long)EE * DEE){ if (!ea) ea = (const float*)d_in[i]; }
        else if (sz == DD * DD)            { if (n16k < 3) w16k[n16k++] = (const float*)d_in[i]; }
        else if (sz == DEE * DD)           { if (!We1) We1 = (const float*)d_in[i]; }
        else if (sz == DD)                 { if (n128 < 12) v128[n128++] = (const float*)d_in[i]; }
    }
    const float *W1 = w16k[0], *W2 = w16k[1], *We2 = w16k[2];
    const float *b1 = v128[0], *g1 = v128[1], *bt1 = v128[2], *m1 = v128[3], *v1 = v128[4];
    const float *b2 = v128[5], *g2 = v128[6], *bt2 = v128[7], *m2 = v128[8], *v2 = v128[9];
    const float *be1 = v128[10], *be2 = v128[11];
    float* out = (float*)d_out;

    static cudaStream_t sB = 0, sC = 0;
    static cudaEvent_t evDinv = 0, evGemm1 = 0, evScan3 = 0, evEdge = 0, evGm2 = 0;
    static cudaEvent_t evG1[NCHUNK] = {0};
    if (!sB) {
        cudaStreamCreateWithFlags(&sB, cudaStreamNonBlocking);
        cudaStreamCreateWithFlags(&sC, cudaStreamNonBlocking);
        cudaEventCreateWithFlags(&evDinv, cudaEventDisableTiming);
        cudaEventCreateWithFlags(&evGemm1, cudaEventDisableTiming);
        cudaEventCreateWithFlags(&evScan3, cudaEventDisableTiming);
        cudaEventCreateWithFlags(&evEdge, cudaEventDisableTiming);
        cudaEventCreateWithFlags(&evGm2, cudaEventDisableTiming);
        for (int i = 0; i < NCHUNK; i++)
            cudaEventCreateWithFlags(&evG1[i], cudaEventDisableTiming);
    }

    const int nb1 = (NN2 + 1023) / 1024;   // 196

    // main: init(+detect) -> converthist -> scan1 (also computes dinv)
    k_initdetect<<<256, 256>>>((const int*)ei);
    k_converthist<<<(EE + 255) / 256, 256>>>(ei);
    k_scan1<<<nb1, 1024>>>();
    cudaEventRecord(evDinv, 0);

    // stream B: layer-1 GEMM (full) overlaps scan2/3 + scatter_dst
    cudaStreamWaitEvent(sB, evDinv, 0);
    k_gemm<true, false><<<(NN + 127) / 128, 256, 0, sB>>>(x, W1, 0, NN);
    cudaEventRecord(evGemm1, sB);

    // main: remaining scans
    k_scan2<<<1, 256>>>(nb1);
    k_scan3<<<nb1, 1024>>>();
    cudaEventRecord(evScan3, 0);

    // stream C: nptr -> scatter_src -> edgemlp
    cudaStreamWaitEvent(sC, evScan3, 0);
    k_nptr<<<1, 512, 0, sC>>>(batch);
    k_scatter_src<<<(EE + 255) / 256, 256, 0, sC>>>();
    k_edgemlp<<<GG * EBLK, 256, 0, sC>>>(ea, We1, be1);
    cudaEventRecord(evEdge, sC);

    // main: dst scatter, join gemm1
    k_scatter_dst<<<(EE + 255) / 256, 256>>>();
    cudaStreamWaitEvent(0, evGemm1, 0);

    // pipelined gather1 (main) / gemm2 (stream B), 2 chunks of 50k nodes
    const int gblocks = ((CHUNKN / 2) * 32 + 255) / 256;
    const int mblocks = (CHUNKN + 127) / 128;
    for (int ci = 0; ci < NCHUNK; ci++) {
        int ns = ci * CHUNKN;
        k_gather<false><<<gblocks, 256>>>(b1, g1, bt1, m1, v1, ns, CHUNKN);
        cudaEventRecord(evG1[ci], 0);
        cudaStreamWaitEvent(sB, evG1[ci], 0);
        k_gemm<false, true><<<mblocks, 256, 0, sB>>>(x, W2, ns, ns + CHUNKN);
    }
    cudaEventRecord(evGm2, sB);

    // gather2 (full) after all gemm2 chunks
    cudaStreamWaitEvent(0, evGm2, 0);
    k_gather<true><<<((NN / 2) * 32 + 255) / 256, 256>>>(b2, g2, bt2, m2, v2, 0, NN);

    // join edge branch, combine
    cudaStreamWaitEvent(0, evEdge, 0);
    k_final<<<GG, 128>>>(We2, be2, out);
}

// round 14
// speedup vs baseline: 1.2301x; 1.2301x over previous
#include <cuda_runtime.h>
#include <cuda_fp16.h>

#define NN 100000
#define NN2 200000
#define DD 128
#define EE 1600000
#define DEE 16
#define GG 512
#define BN_EPS 1e-5f
#define NCHUNK 4
#define CHUNKN 25000
#define SPAD 136
#define GEMM_SMEM (2 * 128 * SPAD * 2)

typedef unsigned long long u64;

// ---------------- f32x2 packed helpers (edge MLP) --------------------------------
__device__ __forceinline__ void ffma2(u64& d, u64 a, u64 b) {
    asm("fma.rn.f32x2 %0, %1, %2, %0;" : "+l"(d) : "l"(a), "l"(b));
}
__device__ __forceinline__ u64 pack_dup(float x) {
    u64 d; unsigned xi = __float_as_uint(x);
    asm("mov.b64 %0, {%1, %1};" : "=l"(d) : "r"(xi));
    return d;
}
__device__ __forceinline__ float2 unpack2(u64 v) {
    unsigned lo, hi;
    asm("mov.b64 {%0, %1}, %2;" : "=r"(lo), "=r"(hi) : "l"(v));
    return make_float2(__uint_as_float(lo), __uint_as_float(hi));
}

// ---------------- scratch (static device globals; no allocation) -----------------
__device__ __align__(16) __half g_bufA[NN * DD];         // layer-1 xw' fp16
__device__ __align__(16) __half g_bufC[NN * DD];         // layer-2 xw' fp16
__device__ __align__(16) float g_bufB[NN * DD];          // h fp32
__device__ __align__(16) __half g_w1t[DD * DD];          // W1^T fp16 [n][k]
__device__ __align__(16) __half g_w2t[DD * DD];          // W2^T fp16 [n][k]
__device__ int   g_deg2[NN2];
__device__ int   g_rowptr[NN + 1];
__device__ int   g_sptr[NN + 1];
__device__ int   g_curn[NN];
__device__ int   g_curs[NN];
__device__ int   g_csrsrc[EE];
__device__ int   g_eid[EE];
__device__ int   g_src32[EE];
__device__ int   g_dst32[EE];
__device__ int   g_egptr[GG + 1];
__device__ int   g_nptr[GG + 1];
__device__ float g_dinv[NN];
__device__ float g_hsum[GG * DD];
__device__ int   g_blksums[256];
__device__ int   g_is64;

// ---------------- index helpers ----------------------------------------------------
__device__ __forceinline__ int load_idx(const void* p, long long i) {
    if (g_is64) return (int)((const long long*)p)[i];
    return ((const int*)p)[i];
}
__device__ __forceinline__ int clampi(int v, int lo, int hi) {
    return v < lo ? lo : (v > hi ? hi : v);
}

// ---------------- init + detect + W->fp16 transpose ----------------------------------
__global__ void k_initdetect(const int* __restrict__ w,
                             const float* __restrict__ W1,
                             const float* __restrict__ W2) {
    if (blockIdx.x == 0) {
        __shared__ int ok;
        if (threadIdx.x == 0) ok = 1;
        __syncthreads();
        int bad = 0;
        for (int i = threadIdx.x; i < 2048; i += blockDim.x)
            if (w[2 * i + 1] != 0) bad = 1;
        if (bad) atomicAnd(&ok, 0);
        __syncthreads();
        if (threadIdx.x == 0) g_is64 = ok;
    }
    int i = blockIdx.x * blockDim.x + threadIdx.x;
    int stride = gridDim.x * blockDim.x;
    for (int j = i; j < NN2; j += stride) g_deg2[j] = 0;
    for (int j = i; j < GG * DD; j += stride) g_hsum[j] = 0.f;
    for (int j = i; j < DD * DD; j += stride) {
        int k = j >> 7, n = j & 127;
        g_w1t[n * DD + k] = __float2half(W1[j]);
        g_w2t[n * DD + k] = __float2half(W2[j]);
    }
}

// ---------------- convert + histogram in one pass --------------------------------------
__global__ void k_converthist(const void* __restrict__ ei) {
    int e = blockIdx.x * blockDim.x + threadIdx.x;
    if (e >= EE) return;
    int s = clampi(load_idx(ei, e), 0, NN - 1);
    int d = clampi(load_idx(ei, (long long)EE + e), 0, NN - 1);
    g_src32[e] = s;
    g_dst32[e] = d;
    atomicAdd(&g_deg2[d], 1);
    atomicAdd(&g_deg2[NN + s], 1);
}

// ---------------- scans (scan1 also emits dinv) ------------------------------------------
__global__ void k_scan1() {
    __shared__ int s[1024];
    int b = blockIdx.x, t = threadIdx.x;
    int i = b * 1024 + t;
    int v = (i < NN2) ? g_deg2[i] : 0;
    if (i < NN) g_dinv[i] = rsqrtf((float)(v + 1));
    s[t] = v;
    __syncthreads();
    for (int off = 1; off < 1024; off <<= 1) {
        int x = (t >= off) ? s[t - off] : 0;
        __syncthreads();
        s[t] += x;
        __syncthreads();
    }
    if (i < NN2) {
        if (i < NN) g_rowptr[i] = s[t] - v;
        else        g_sptr[i - NN] = s[t] - v;
    }
    if (t == 1023) g_blksums[b] = s[t];
}

__global__ void k_scan2(int nb) {
    __shared__ int s[256];
    int t = threadIdx.x;
    int v = (t < nb) ? g_blksums[t] : 0;
    s[t] = v;
    __syncthreads();
    for (int off = 1; off < 256; off <<= 1) {
        int x = (t >= off) ? s[t - off] : 0;
        __syncthreads();
        s[t] += x;
        __syncthreads();
    }
    g_blksums[t] = s[t] - v;
}

__global__ void k_scan3() {
    int b = blockIdx.x, t = threadIdx.x;
    int i = b * 1024 + t;
    if (i < NN2) {
        int add = g_blksums[b];
        if (i < NN) {
            int rp = g_rowptr[i] + add;
            g_rowptr[i] = rp;
            g_curn[i] = rp;
        } else {
            int sp = g_sptr[i - NN] + add - EE;
            g_sptr[i - NN] = sp;
            g_curs[i - NN] = sp;
        }
    }
    if (i == 0) { g_rowptr[NN] = EE; g_sptr[NN] = EE; }
}

// ---------------- nptr via binary search -----------------------------------------------
__global__ void k_nptr(const void* __restrict__ batch) {
    int g = threadIdx.x;    // 512
    int lo = 0, hi = NN;
    while (lo < hi) {
        int mid = (lo + hi) >> 1;
        if (load_idx(batch, mid) < g) lo = mid + 1;
        else hi = mid;
    }
    g_nptr[g] = lo;
    g_egptr[g] = g_sptr[lo];
    if (g == 0) { g_nptr[GG] = NN; g_egptr[GG] = EE; }
}

// ---------------- CSR scatters ------------------------------------------------------------
__global__ void k_scatter_dst() {
    int e = blockIdx.x * blockDim.x + threadIdx.x;
    if (e >= EE) return;
    int s = g_src32[e];
    int d = g_dst32[e];
    int p = atomicAdd(&g_curn[d], 1);
    if (p >= 0 && p < EE) g_csrsrc[p] = s;
}

__global__ void k_scatter_src() {
    int e = blockIdx.x * blockDim.x + threadIdx.x;
    if (e >= EE) return;
    int s = g_src32[e];
    int p2 = atomicAdd(&g_curs[s], 1);
    if (p2 >= 0 && p2 < EE) g_eid[p2] = e;
}

// ---------------- GEMM via tensor cores (HMMA m16n8k16, fp32 accum) -------------------------
// block: 256 thr = 8 warps; tile 128x128, full K=128 in smem.
// warp (wm=warp>>1, wn=warp&1) computes rows wm*32..+31, cols wn*64..+63.
template <bool FIRST, bool OUTC>
__global__ void __launch_bounds__(256)
k_gemm(const float* __restrict__ Xext, int rstart, int rend) {
    const float* __restrict__ X = FIRST ? Xext : (const float*)g_bufB;
    const __half* __restrict__ Wt = FIRST ? g_w1t : g_w2t;
    __half* __restrict__ Y = OUTC ? g_bufC : g_bufA;
    extern __shared__ __half smem[];
    __half (*xs)[SPAD] = reinterpret_cast<__half(*)[SPAD]>(smem);
    __half (*wt)[SPAD] = reinterpret_cast<__half(*)[SPAD]>(smem + 128 * SPAD);

    int tid = threadIdx.x;
    int warp = tid >> 5, lane = tid & 31;
    int g = lane >> 2, tig = lane & 3;
    int wm = warp >> 1, wn = warp & 1;
    int row0 = rstart + blockIdx.x * 128;

    // fill wt (fp16, already transposed in gmem): 2048 uint4, 8 per thread, coalesced
    const uint4* wt4 = reinterpret_cast<const uint4*>(Wt);
#pragma unroll
    for (int l = 0; l < 8; l++) {
        int idx = tid + l * 256;
        int n = idx >> 4;
        int kq = idx & 15;
        *reinterpret_cast<uint4*>(&wt[n][kq * 8]) = wt4[idx];
    }
    // fill xs: fp32 -> fp16, 4096 float4, 16 per thread, coalesced
#pragma unroll
    for (int l = 0; l < 16; l++) {
        int idx = tid + l * 256;
        int r = idx >> 5;
        int cq = idx & 31;
        float4 v = make_float4(0.f, 0.f, 0.f, 0.f);
        int grow = row0 + r;
        if (grow < rend) v = *reinterpret_cast<const float4*>(&X[grow * DD + cq * 4]);
        *reinterpret_cast<__half2*>(&xs[r][cq * 4])     = __floats2half2_rn(v.x, v.y);
        *reinterpret_cast<__half2*>(&xs[r][cq * 4 + 2]) = __floats2half2_rn(v.z, v.w);
    }
    __syncthreads();

    float c[2][8][4];
#pragma unroll
    for (int mt = 0; mt < 2; mt++)
#pragma unroll
        for (int nt = 0; nt < 8; nt++)
#pragma unroll
            for (int i = 0; i < 4; i++) c[mt][nt][i] = 0.f;

#pragma unroll
    for (int ks = 0; ks < 8; ks++) {
        int k0 = ks * 16;
        unsigned a[2][4];
#pragma unroll
        for (int mt = 0; mt < 2; mt++) {
            int rb = wm * 32 + mt * 16;
            a[mt][0] = *reinterpret_cast<unsigned*>(&xs[rb + g][k0 + tig * 2]);
            a[mt][1] = *reinterpret_cast<unsigned*>(&xs[rb + g + 8][k0 + tig * 2]);
            a[mt][2] = *reinterpret_cast<unsigned*>(&xs[rb + g][k0 + tig * 2 + 8]);
            a[mt][3] = *reinterpret_cast<unsigned*>(&xs[rb + g + 8][k0 + tig * 2 + 8]);
        }
#pragma unroll
        for (int nt = 0; nt < 8; nt++) {
            int n = wn * 64 + nt * 8 + g;
            unsigned b0 = *reinterpret_cast<unsigned*>(&wt[n][k0 + tig * 2]);
            unsigned b1 = *reinterpret_cast<unsigned*>(&wt[n][k0 + tig * 2 + 8]);
#pragma unroll
            for (int mt = 0; mt < 2; mt++) {
                asm volatile(
                    "mma.sync.aligned.m16n8k16.row.col.f32.f16.f16.f32 "
                    "{%0,%1,%2,%3}, {%4,%5,%6,%7}, {%8,%9}, {%0,%1,%2,%3};"
                    : "+f"(c[mt][nt][0]), "+f"(c[mt][nt][1]),
                      "+f"(c[mt][nt][2]), "+f"(c[mt][nt][3])
                    : "r"(a[mt][0]), "r"(a[mt][1]), "r"(a[mt][2]), "r"(a[mt][3]),
                      "r"(b0), "r"(b1));
            }
        }
    }

    // epilogue: scale by dinv, pack fp16
#pragma unroll
    for (int mt = 0; mt < 2; mt++) {
        int r0 = wm * 32 + mt * 16 + g;
        int grow0 = row0 + r0;
        int grow1 = grow0 + 8;
        float d0 = (grow0 < rend) ? g_dinv[grow0] : 0.f;
        float d1 = (grow1 < rend) ? g_dinv[grow1] : 0.f;
#pragma unroll
        for (int nt = 0; nt < 8; nt++) {
            int col = wn * 64 + nt * 8 + tig * 2;
            if (grow0 < rend)
                *reinterpret_cast<__half2*>(&Y[grow0 * DD + col]) =
                    __floats2half2_rn(c[mt][nt][0] * d0, c[mt][nt][1] * d0);
            if (grow1 < rend)
                *reinterpret_cast<__half2*>(&Y[grow1 * DD + col]) =
                    __floats2half2_rn(c[mt][nt][2] * d1, c[mt][nt][3] * d1);
        }
    }
}

// ---------------- gather (fp16 payload, one node/warp, 8-deep unroll) ----------------------
__device__ __forceinline__ void addu2(float4& a, uint2 u) {
    float2 fa = __half22float2(*reinterpret_cast<__half2*>(&u.x));
    float2 fb = __half22float2(*reinterpret_cast<__half2*>(&u.y));
    a.x += fa.x; a.y += fa.y; a.z += fb.x; a.w += fb.y;
}
template <bool SRCC>
__global__ void k_gather(const float* __restrict__ B, const float* __restrict__ GA,
                         const float* __restrict__ BT, const float* __restrict__ M,
                         const float* __restrict__ V, int nstart, int ncount) {
    int w = (blockIdx.x * blockDim.x + threadIdx.x) >> 5;
    int lane = threadIdx.x & 31;
    if (w >= ncount) return;
    int node = nstart + w;
    float di = g_dinv[node];
    const uint2* xw2 = reinterpret_cast<const uint2*>(SRCC ? (const __half*)g_bufC
                                                           : (const __half*)g_bufA);
    float4 A0, A1, A2, A3;
    A1 = A2 = A3 = make_float4(0.f, 0.f, 0.f, 0.f);
    A0 = make_float4(0.f, 0.f, 0.f, 0.f);
    addu2(A0, xw2[node * 32 + lane]);   // self term
    int jb = g_rowptr[node], je = g_rowptr[node + 1];
    int j = jb;
    for (; j + 7 < je; j += 8) {
        uint2 u0 = xw2[g_csrsrc[j + 0] * 32 + lane];
        uint2 u1 = xw2[g_csrsrc[j + 1] * 32 + lane];
        uint2 u2 = xw2[g_csrsrc[j + 2] * 32 + lane];
        uint2 u3 = xw2[g_csrsrc[j + 3] * 32 + lane];
        uint2 u4 = xw2[g_csrsrc[j + 4] * 32 + lane];
        uint2 u5 = xw2[g_csrsrc[j + 5] * 32 + lane];
        uint2 u6 = xw2[g_csrsrc[j + 6] * 32 + lane];
        uint2 u7 = xw2[g_csrsrc[j + 7] * 32 + lane];
        addu2(A0, u0); addu2(A1, u1); addu2(A2, u2); addu2(A3, u3);
        addu2(A0, u4); addu2(A1, u5); addu2(A2, u6); addu2(A3, u7);
    }
    for (; j < je; j++) addu2(A0, xw2[g_csrsrc[j] * 32 + lane]);
    float4 acc;
    acc.x = (A0.x + A1.x) + (A2.x + A3.x);
    acc.y = (A0.y + A1.y) + (A2.y + A3.y);
    acc.z = (A0.z + A1.z) + (A2.z + A3.z);
    acc.w = (A0.w + A1.w) + (A2.w + A3.w);
    int f = lane * 4;
    float4 b4  = *reinterpret_cast<const float4*>(&B[f]);
    float4 g4  = *reinterpret_cast<const float4*>(&GA[f]);
    float4 bt4 = *reinterpret_cast<const float4*>(&BT[f]);
    float4 m4  = *reinterpret_cast<const float4*>(&M[f]);
    float4 vv4 = *reinterpret_cast<const float4*>(&V[f]);
    float4 o;
    o.x = fmaxf((acc.x * di + b4.x - m4.x) * rsqrtf(vv4.x + BN_EPS) * g4.x + bt4.x, 0.f);
    o.y = fmaxf((acc.y * di + b4.y - m4.y) * rsqrtf(vv4.y + BN_EPS) * g4.y + bt4.y, 0.f);
    o.z = fmaxf((acc.z * di + b4.z - m4.z) * rsqrtf(vv4.z + BN_EPS) * g4.z + bt4.z, 0.f);
    o.w = fmaxf((acc.w * di + b4.w - m4.w) * rsqrtf(vv4.w + BN_EPS) * g4.w + bt4.w, 0.f);
    float4* out4 = reinterpret_cast<float4*>((float*)g_bufB);
    out4[node * 32 + lane] = o;
}

// ---------------- edge MLP first layer, summed per graph (FFMA2, 2-edge ILP) -----------------
#define EBLK 8
__global__ void k_edgemlp(const float* __restrict__ EA, const float* __restrict__ W1e,
                          const float* __restrict__ B1e) {
    int g = blockIdx.x >> 3;
    int q = blockIdx.x & (EBLK - 1);
    int tid = threadIdx.x, warp = tid >> 5, lane = tid & 31;
    __shared__ float eas[8][2][16];
    __shared__ float red[DD];
    ulonglong2 wc[16];
#pragma unroll
    for (int k = 0; k < 16; k++)
        wc[k] = *reinterpret_cast<const ulonglong2*>(&W1e[k * DD + lane * 4]);
    ulonglong2 b2 = *reinterpret_cast<const ulonglong2*>(&B1e[lane * 4]);

    int gb = g_egptr[g], ge = g_egptr[g + 1];
    int cnt = ge - gb;
    int per = (cnt + EBLK - 1) / EBLK;
    int jb = gb + q * per;
    int je = min(jb + per, ge);

    float4 acc = make_float4(0.f, 0.f, 0.f, 0.f);
    for (int j = jb + warp; j < je; j += 16) {
        int j2 = j + 8;
        bool has2 = (j2 < je);
        int e0 = g_eid[j];
        int e1 = has2 ? g_eid[j2] : e0;
        if (lane < 16) eas[warp][0][lane] = EA[(long long)e0 * DEE + lane];
        else           eas[warp][1][lane - 16] = EA[(long long)e1 * DEE + (lane - 16)];
        __syncwarp();
        u64 h0 = b2.x, h1 = b2.y, h2 = b2.x, h3 = b2.y;
#pragma unroll
        for (int k = 0; k < 16; k++) {
            u64 p0 = pack_dup(eas[warp][0][k]);
            u64 p1 = pack_dup(eas[warp][1][k]);
            ffma2(h0, p0, wc[k].x);
            ffma2(h1, p0, wc[k].y);
            ffma2(h2, p1, wc[k].x);
            ffma2(h3, p1, wc[k].y);
        }
        float2 u0 = unpack2(h0), u1 = unpack2(h1);
        acc.x += fmaxf(u0.x, 0.f);
        acc.y += fmaxf(u0.y, 0.f);
        acc.z += fmaxf(u1.x, 0.f);
        acc.w += fmaxf(u1.y, 0.f);
        if (has2) {
            float2 u2 = unpack2(h2), u3 = unpack2(h3);
            acc.x += fmaxf(u2.x, 0.f);
            acc.y += fmaxf(u2.y, 0.f);
            acc.z += fmaxf(u3.x, 0.f);
            acc.w += fmaxf(u3.y, 0.f);
        }
        __syncwarp();
    }
    if (tid < DD) red[tid] = 0.f;
    __syncthreads();
    int f = lane * 4;
    atomicAdd(&red[f + 0], acc.x);
    atomicAdd(&red[f + 1], acc.y);
    atomicAdd(&red[f + 2], acc.z);
    atomicAdd(&red[f + 3], acc.w);
    __syncthreads();
    if (tid < DD) atomicAdd(&g_hsum[g * DD + tid], red[tid]);
}

// ---------------- final combine -------------------------------------------------------------
__global__ void k_final(const float* __restrict__ We2, const float* __restrict__ be2,
                        float* __restrict__ out) {
    int g = blockIdx.x;
    int t = threadIdx.x;   // 128
    __shared__ float hm[DD];
    int ec = g_egptr[g + 1] - g_egptr[g];
    float inv_e = (ec > 0) ? (1.f / (float)ec) : 0.f;
    hm[t] = g_hsum[g * DD + t] * inv_e;

    int ns = g_nptr[g], ne = g_nptr[g + 1];
    const float* __restrict__ H = (const float*)g_bufB;
    float a0 = 0.f, a1 = 0.f, a2 = 0.f, a3 = 0.f;
    int rr = ns;
    for (; rr + 3 < ne; rr += 4) {
        a0 += H[(long long)rr * DD + t];
        a1 += H[(long long)(rr + 1) * DD + t];
        a2 += H[(long long)(rr + 2) * DD + t];
        a3 += H[(long long)(rr + 3) * DD + t];
    }
    for (; rr < ne; rr++) a0 += H[(long long)rr * DD + t];
    float nsumv = (a0 + a1) + (a2 + a3);

    __syncthreads();
    float acc = be2[t];
#pragma unroll 4
    for (int k = 0; k < DD; k++)
        acc = fmaf(hm[k], We2[k * DD + t], acc);
    if (ec == 0) acc = 0.f;
    int nc = ne - ns;
    float gr = nsumv / fmaxf((float)nc, 1.f);
    out[g * DD + t] = gr + acc;
}

// ---------------- launch ------------------------------------------------------------------------
extern "C" void kernel_launch(void* const* d_in, const int* in_sizes, int n_in,
                              void* d_out, int out_size) {
    const float* x = 0;  const void* ei = 0;  const void* batch = 0;  const float* ea = 0;
    const float* w16k[3] = {0, 0, 0};
    const float* v128[12] = {0};
    const float* We1 = 0;
    int n16k = 0, n128 = 0;
    for (int i = 0; i < n_in; i++) {
        long long sz = in_sizes[i];
        if      (sz == (long long)NN * DD) { if (!x) x = (const float*)d_in[i]; }
        else if (sz == 2LL * EE)           { if (!ei) ei = d_in[i]; }
        else if (sz == NN)                 { if (!batch) batch = d_in[i]; }
        else if (sz == (long long)EE * DEE){ if (!ea) ea = (const float*)d_in[i]; }
        else if (sz == DD * DD)            { if (n16k < 3) w16k[n16k++] = (const float*)d_in[i]; }
        else if (sz == DEE * DD)           { if (!We1) We1 = (const float*)d_in[i]; }
        else if (sz == DD)                 { if (n128 < 12) v128[n128++] = (const float*)d_in[i]; }
    }
    const float *W1 = w16k[0], *W2 = w16k[1], *We2 = w16k[2];
    const float *b1 = v128[0], *g1 = v128[1], *bt1 = v128[2], *m1 = v128[3], *v1 = v128[4];
    const float *b2 = v128[5], *g2 = v128[6], *bt2 = v128[7], *m2 = v128[8], *v2 = v128[9];
    const float *be1 = v128[10], *be2 = v128[11];
    float* out = (float*)d_out;

    static cudaStream_t sB = 0, sC = 0;
    static cudaEvent_t evDinv = 0, evGemm1 = 0, evScan3 = 0, evEdge = 0, evGm2 = 0;
    static cudaEvent_t evG1[NCHUNK] = {0};
    if (!sB) {
        cudaStreamCreateWithFlags(&sB, cudaStreamNonBlocking);
        cudaStreamCreateWithFlags(&sC, cudaStreamNonBlocking);
        cudaEventCreateWithFlags(&evDinv, cudaEventDisableTiming);
        cudaEventCreateWithFlags(&evGemm1, cudaEventDisableTiming);
        cudaEventCreateWithFlags(&evScan3, cudaEventDisableTiming);
        cudaEventCreateWithFlags(&evEdge, cudaEventDisableTiming);
        cudaEventCreateWithFlags(&evGm2, cudaEventDisableTiming);
        for (int i = 0; i < NCHUNK; i++)
            cudaEventCreateWithFlags(&evG1[i], cudaEventDisableTiming);
        cudaFuncSetAttribute(k_gemm<true, false>,
                             cudaFuncAttributeMaxDynamicSharedMemorySize, GEMM_SMEM);
        cudaFuncSetAttribute(k_gemm<false, true>,
                             cudaFuncAttributeMaxDynamicSharedMemorySize, GEMM_SMEM);
    }

    const int nb1 = (NN2 + 1023) / 1024;   // 196

    // main: init(+detect+Wfp16) -> converthist -> scan1 (emits dinv)
    k_initdetect<<<256, 256>>>((const int*)ei, W1, W2);
    k_converthist<<<(EE + 255) / 256, 256>>>(ei);
    k_scan1<<<nb1, 1024>>>();
    cudaEventRecord(evDinv, 0);

    // stream B: layer-1 GEMM (tensor cores) overlaps scans + scatter_dst   [profiled slot #4]
    cudaStreamWaitEvent(sB, evDinv, 0);
    k_gemm<true, false><<<(NN + 127) / 128, 256, GEMM_SMEM, sB>>>(x, 0, NN);
    cudaEventRecord(evGemm1, sB);

    // main: remaining scans
    k_scan2<<<1, 256>>>(nb1);
    k_scan3<<<nb1, 1024>>>();
    cudaEventRecord(evScan3, 0);

    // stream C: nptr -> scatter_src -> edgemlp
    cudaStreamWaitEvent(sC, evScan3, 0);
    k_nptr<<<1, 512, 0, sC>>>(batch);
    k_scatter_src<<<(EE + 255) / 256, 256, 0, sC>>>();
    k_edgemlp<<<GG * EBLK, 256, 0, sC>>>(ea, We1, be1);
    cudaEventRecord(evEdge, sC);

    // main: dst scatter, join gemm1
    k_scatter_dst<<<(EE + 255) / 256, 256>>>();
    cudaStreamWaitEvent(0, evGemm1, 0);

    // pipelined gather1 (main) / gemm2 (stream B), 4 chunks of 25k nodes
    const int gblocks = (CHUNKN * 32 + 255) / 256;
    const int mblocks = (CHUNKN + 127) / 128;
    for (int ci = 0; ci < NCHUNK; ci++) {
        int ns = ci * CHUNKN;
        k_gather<false><<<gblocks, 256>>>(b1, g1, bt1, m1, v1, ns, CHUNKN);
        cudaEventRecord(evG1[ci], 0);
        cudaStreamWaitEvent(sB, evG1[ci], 0);
        k_gemm<false, true><<<mblocks, 256, GEMM_SMEM, sB>>>(x, ns, ns + CHUNKN);
    }
    cudaEventRecord(evGm2, sB);

    // gather2 (full) after all gemm2 chunks
    cudaStreamWaitEvent(0, evGm2, 0);
    k_gather<true><<<(NN * 32 + 255) / 256, 256>>>(b2, g2, bt2, m2, v2, 0, NN);

    // join edge branch, combine
    cudaStreamWaitEvent(0, evEdge, 0);
    k_final<<<GG, 128>>>(We2, be2, out);
}